// round 2
// baseline (speedup 1.0000x reference)
#include <cuda_runtime.h>
#include <cstdint>

// 8x8 confusion-matrix bins (counts), device-global scratch.
__device__ unsigned int g_cm[64];

#define N_CATS 8

__global__ void qwk_zero_kernel() {
    int t = threadIdx.x;
    if (t < 64) g_cm[t] = 0u;
}

// Histogram kernel: pred = argmax of 8 logits; bin = t*8+pred if t > 0.
// Per-block shared histogram, flushed with 64 global atomics.
__global__ __launch_bounds__(256) void qwk_hist_kernel(
    const float4* __restrict__ logits4,   // 2 float4 per element
    const int* __restrict__ targets,      // int32 (JAX x64 disabled)
    int n_elems)
{
    __shared__ unsigned int s_cm[64];
    int tid = threadIdx.x;
    if (tid < 64) s_cm[tid] = 0u;
    __syncthreads();

    int stride = gridDim.x * blockDim.x;
    for (int i = blockIdx.x * blockDim.x + tid; i < n_elems; i += stride) {
        float4 a = logits4[2 * i];
        float4 b = logits4[2 * i + 1];
        int tv = targets[i];

        // argmax of 8, first-max-wins (strict >)
        int best = 0; float m = a.x;
        if (a.y > m) { m = a.y; best = 1; }
        if (a.z > m) { m = a.z; best = 2; }
        if (a.w > m) { m = a.w; best = 3; }
        if (b.x > m) { m = b.x; best = 4; }
        if (b.y > m) { m = b.y; best = 5; }
        if (b.z > m) { m = b.z; best = 6; }
        if (b.w > m) { m = b.w; best = 7; }

        if (tv > 0 && tv < N_CATS) {
            atomicAdd(&s_cm[tv * N_CATS + best], 1u);
        }
    }
    __syncthreads();
    if (tid < 64) {
        unsigned int c = s_cm[tid];
        if (c) atomicAdd(&g_cm[tid], c);
    }
}

// Finalize: tiny 8x8 QWK algebra, single thread.
__global__ void qwk_finalize_kernel(float* __restrict__ out) {
    if (threadIdx.x != 0 || blockIdx.x != 0) return;

    float cm[64];
    float n = 0.0f;
    #pragma unroll
    for (int i = 0; i < 64; i++) {
        cm[i] = (float)g_cm[i];
        n += cm[i];
    }

    if (n == 0.0f) {            // qwk = 1 -> loss = 0
        out[0] = 0.0f;
        return;
    }

    float inv_n = 1.0f / n;
    #pragma unroll
    for (int i = 0; i < 64; i++) cm[i] *= inv_n;

    float mt[8], mp[8];
    #pragma unroll
    for (int i = 0; i < 8; i++) { mt[i] = 0.0f; mp[i] = 0.0f; }
    #pragma unroll
    for (int i = 0; i < 8; i++)
        #pragma unroll
        for (int j = 0; j < 8; j++) {
            mt[i] += cm[i * 8 + j];
            mp[j] += cm[i * 8 + j];
        }

    const float inv_d2 = 1.0f / 49.0f;  // (n_cats-1)^2 = 49
    float num = 0.0f, den = 0.0f;
    #pragma unroll
    for (int i = 0; i < 8; i++) {
        #pragma unroll
        for (int j = 0; j < 8; j++) {
            float d = (float)(i - j);
            float w = 1.0f - d * d * inv_d2;
            num += w * cm[i * 8 + j];
            den += w * mt[i] * mp[j];
        }
    }

    float qwk = (den == 0.0f) ? 0.0f : (num / den);
    out[0] = 1.0f - qwk;
}

extern "C" void kernel_launch(void* const* d_in, const int* in_sizes, int n_in,
                              void* d_out, int out_size) {
    const float4* logits4 = (const float4*)d_in[0];
    const int* targets = (const int*)d_in[1];
    float* out = (float*)d_out;
    int n_elems = in_sizes[1];   // B*S = 2048*4096

    qwk_zero_kernel<<<1, 64>>>();

    int threads = 256;
    int blocks = 1184;           // 8 blocks/SM * 148 SMs
    qwk_hist_kernel<<<blocks, threads>>>(logits4, targets, n_elems);

    qwk_finalize_kernel<<<1, 32>>>(out);
}